// round 1
// baseline (speedup 1.0000x reference)
#include <cuda_runtime.h>

#define NUMB 32
#define LDIM 128
#define DDIM 256
#define HDIM 256
#define BAG  300
#define POOL 1200

// Transposed hidden activations: [side][n][h][a]  (a fastest)
__device__ float g_hT[2][NUMB * HDIM * LDIM];

// ---------------------------------------------------------------------------
// Kernel A: gather + GEMM  h[side][n,a,:] = f[side][n,a,:] @ W1 (+ b1 if side 1)
// Stored transposed as g_hT[side][n][h][a].
// Block: (rt, side, n); 256 threads, thread t = h column, 16 rows per block.
// ---------------------------------------------------------------------------
__global__ void __launch_bounds__(256) gemm_kernel(
    const float* __restrict__ fea,
    const int*   __restrict__ ind0,
    const int*   __restrict__ ind1,
    const float* __restrict__ W1a,
    const float* __restrict__ W1b,
    const float* __restrict__ b1)
{
    const int rt = blockIdx.x;     // row tile 0..7 (16 rows each)
    const int side = blockIdx.y;   // 0 or 1
    const int n = blockIdx.z;      // 0..31
    const int t = threadIdx.x;     // h column 0..255

    __shared__ float fs[16][DDIM];

    const int*   ind = side ? ind1 : ind0;
    const float* W1  = side ? W1b  : W1a;

    // Gather 16 feature rows into shared (coalesced over d = t)
    #pragma unroll
    for (int r = 0; r < 16; r++) {
        int a   = rt * 16 + r;
        int top = a >> 2, c = a & 3;
        int id  = ind[(n * 32 + top) * 4 + c] + BAG * c;
        int row = (n * 2 + side) * POOL + id;
        fs[r][t] = fea[(size_t)row * DDIM + t];
    }
    __syncthreads();

    float acc[16];
    #pragma unroll
    for (int r = 0; r < 16; r++) acc[r] = 0.f;

    #pragma unroll 4
    for (int d = 0; d < DDIM; d++) {
        float w = __ldg(&W1[d * HDIM + t]);
        #pragma unroll
        for (int r = 0; r < 16; r++)
            acc[r] = fmaf(fs[r][d], w, acc[r]);
    }

    const float bias = side ? b1[t] : 0.f;
    float* out = &g_hT[side][(n * HDIM + t) * LDIM + rt * 16];
    #pragma unroll
    for (int r = 0; r < 16; r++) out[r] = acc[r] + bias;
}

// ---------------------------------------------------------------------------
// Kernel B: pairwise relu-score + fused 4x4 patch sum.
// out[n,i,j] = sum_{r,s in 0..3} sum_h relu(h0[n,4i+r,h]+h1[n,4j+s,h]) * W2[h]
//              + 16*b2
// Block: (quad, n); 256 threads; thread (ty,tx) owns one (i,j) output scalar.
// Block covers 16x16 patches = 64x64 pairs; H processed in 4 chunks of 64.
// ---------------------------------------------------------------------------
__global__ void __launch_bounds__(256) pair_kernel(
    const float* __restrict__ W2,
    const float* __restrict__ b2,
    float*       __restrict__ out)
{
    const int n  = blockIdx.y;
    const int qa = blockIdx.x >> 1;
    const int qb = blockIdx.x & 1;
    const int tx = threadIdx.x & 15;   // j within quadrant
    const int ty = threadIdx.x >> 4;   // i within quadrant

    __shared__ float h0s[64][64];   // [h_local][a_local]
    __shared__ float h1s[64][64];   // [h_local][b_local]
    __shared__ float w2s[HDIM];

    w2s[threadIdx.x] = W2[threadIdx.x];

    const float* h0g = &g_hT[0][(size_t)n * HDIM * LDIM];
    const float* h1g = &g_hT[1][(size_t)n * HDIM * LDIM];

    float acc = 0.f;

    for (int ch = 0; ch < 4; ch++) {
        __syncthreads();
        // Load 64x64 tiles, coalesced (a fastest in global layout)
        #pragma unroll
        for (int i = 0; i < 16; i++) {
            int idx = i * 256 + threadIdx.x;
            int hl = idx >> 6, al = idx & 63;
            h0s[hl][al] = h0g[(ch * 64 + hl) * LDIM + qa * 64 + al];
            h1s[hl][al] = h1g[(ch * 64 + hl) * LDIM + qb * 64 + al];
        }
        __syncthreads();

        #pragma unroll 4
        for (int hh = 0; hh < 64; hh++) {
            float4 a4 = *(const float4*)&h0s[hh][ty * 4];
            float4 b4 = *(const float4*)&h1s[hh][tx * 4];
            float A[4] = {a4.x, a4.y, a4.z, a4.w};
            float B[4] = {b4.x, b4.y, b4.z, b4.w};
            float s = 0.f;
            #pragma unroll
            for (int u = 0; u < 4; u++)
                #pragma unroll
                for (int v = 0; v < 4; v++)
                    s += fmaxf(A[u] + B[v], 0.f);
            acc = fmaf(w2s[ch * 64 + hh], s, acc);
        }
    }

    acc += 16.0f * b2[0];
    const int I = qa * 16 + ty;
    const int J = qb * 16 + tx;
    out[n * 1024 + I * 32 + J] = acc;
}

// ---------------------------------------------------------------------------
// Kernel C: constant pairs tensor: pairs[n,p] = (p/32, p%32), as floats.
// ---------------------------------------------------------------------------
__global__ void pairs_kernel(float* __restrict__ out)
{
    int tid = blockIdx.x * blockDim.x + threadIdx.x;
    if (tid < 32 * 1024) {
        int p = tid & 1023;
        out[32768 + 2 * tid]     = (float)(p >> 5);
        out[32768 + 2 * tid + 1] = (float)(p & 31);
    }
}

extern "C" void kernel_launch(void* const* d_in, const int* in_sizes, int n_in,
                              void* d_out, int out_size)
{
    const float* fea  = (const float*)d_in[0];
    const int*   ind0 = (const int*)  d_in[1];
    const int*   ind1 = (const int*)  d_in[2];

    // "k" may or may not be materialized as input index 3 (scalar, size 1).
    int base = 3;
    if (n_in >= 9 && in_sizes[3] == 1) base = 4;

    const float* W1a = (const float*)d_in[base + 0];
    const float* W1b = (const float*)d_in[base + 1];
    const float* b1  = (const float*)d_in[base + 2];
    const float* W2  = (const float*)d_in[base + 3];
    const float* b2  = (const float*)d_in[base + 4];

    float* out = (float*)d_out;

    gemm_kernel<<<dim3(8, 2, NUMB), 256>>>(fea, ind0, ind1, W1a, W1b, b1);
    pair_kernel<<<dim3(4, NUMB), 256>>>(W2, b2, out);
    if (out_size >= 98304) {
        pairs_kernel<<<128, 256>>>(out);
    }
}

// round 6
// speedup vs baseline: 1.2791x; 1.2791x over previous
#include <cuda_runtime.h>

#define NUMB 32
#define LDIM 128
#define DDIM 256
#define HDIM 256
#define BAG  300
#define POOL 1200

// Hidden activations, natural layout: [side][n*128 + a][h]
__device__ float g_h[2][NUMB * LDIM * HDIM];

// ---------------------------------------------------------------------------
// Kernel A: gather + GEMM  h[side][n,a,:] = f[side][n,a,:] @ W1 (+ b1 if side)
// Block: (rt, side, n); 256 threads. Tile: 16 rows x 256 h-cols.
// Thread: rh = tid>>7 selects 8 rows, cx = tid&127 selects h-cols {2cx, 2cx+1}.
// Inner: per 4 k-steps: 8 LDS.128 + 4 LDG.64 + 64 FFMA.
// ---------------------------------------------------------------------------
__global__ void __launch_bounds__(256, 3) gemm_kernel(
    const float* __restrict__ fea,
    const int*   __restrict__ ind0,
    const int*   __restrict__ ind1,
    const float* __restrict__ W1a,
    const float* __restrict__ W1b,
    const float* __restrict__ b1)
{
    const int rt   = blockIdx.x;   // row tile 0..7 (16 rows each)
    const int side = blockIdx.y;   // 0 or 1
    const int n    = blockIdx.z;   // 0..31
    const int tid  = threadIdx.x;
    const int cx   = tid & 127;    // h pair index -> cols 2cx, 2cx+1
    const int rh   = tid >> 7;     // row half (0/1)

    __shared__ float fs[16][DDIM];

    const int*   ind = side ? ind1 : ind0;
    const float* W1  = side ? W1b  : W1a;

    // Gather 16 feature rows into shared (coalesced over d)
    #pragma unroll
    for (int r = 0; r < 16; r++) {
        int a   = rt * 16 + r;
        int top = a >> 2, c = a & 3;
        int id  = ind[(n * 32 + top) * 4 + c] + BAG * c;
        int row = (n * 2 + side) * POOL + id;
        fs[r][tid] = fea[(size_t)row * DDIM + tid];
    }
    __syncthreads();

    float acc0[8], acc1[8];
    #pragma unroll
    for (int r = 0; r < 8; r++) { acc0[r] = 0.f; acc1[r] = 0.f; }

    const float* Wp = W1 + 2 * cx;
    const int r0 = rh * 8;

    #pragma unroll 2
    for (int d = 0; d < DDIM; d += 4) {
        float2 w0 = *(const float2*)(Wp + (size_t)(d + 0) * HDIM);
        float2 w1 = *(const float2*)(Wp + (size_t)(d + 1) * HDIM);
        float2 w2 = *(const float2*)(Wp + (size_t)(d + 2) * HDIM);
        float2 w3 = *(const float2*)(Wp + (size_t)(d + 3) * HDIM);
        #pragma unroll
        for (int r = 0; r < 8; r++) {
            float4 f = *(const float4*)&fs[r0 + r][d];
            acc0[r] = fmaf(f.x, w0.x, acc0[r]);
            acc1[r] = fmaf(f.x, w0.y, acc1[r]);
            acc0[r] = fmaf(f.y, w1.x, acc0[r]);
            acc1[r] = fmaf(f.y, w1.y, acc1[r]);
            acc0[r] = fmaf(f.z, w2.x, acc0[r]);
            acc1[r] = fmaf(f.z, w2.y, acc1[r]);
            acc0[r] = fmaf(f.w, w3.x, acc0[r]);
            acc1[r] = fmaf(f.w, w3.y, acc1[r]);
        }
    }

    float2 bias = make_float2(0.f, 0.f);
    if (side) bias = *(const float2*)(b1 + 2 * cx);

    #pragma unroll
    for (int r = 0; r < 8; r++) {
        int row = rt * 16 + r0 + r;   // a index 0..127
        float2 v = make_float2(acc0[r] + bias.x, acc1[r] + bias.y);
        *(float2*)&g_h[side][((size_t)(n * LDIM + row)) * HDIM + 2 * cx] = v;
    }
}

// ---------------------------------------------------------------------------
// Kernel B: pairwise relu-score + fused 4x4 patch sum.
// out[n,I,J] = sum_{u,v<4} sum_h relu(h0[n,4I+u,h]+h1[n,4J+v,h]) * W2[h] + 16 b2
// Block: (quad, n); 512 threads. Block covers 64x64 pairs (16x16 patches).
// hp = tid>>8 splits the u-dimension (2 u's each); shared reduce at the end.
// H processed in 8 chunks of 32 (tiles stay under 48KB static smem).
// ---------------------------------------------------------------------------
__global__ void __launch_bounds__(512) pair_kernel(
    const float* __restrict__ W2,
    const float* __restrict__ b2,
    float*       __restrict__ out)
{
    const int n  = blockIdx.y;
    const int qa = blockIdx.x >> 1;
    const int qb = blockIdx.x & 1;
    const int tid = threadIdx.x;
    const int hp = tid >> 8;          // 0/1: which u-pair
    const int t2 = tid & 255;
    const int tx = t2 & 15;           // J patch within quadrant
    const int ty = t2 >> 4;           // I patch within quadrant

    __shared__ float h0s[64][33];     // [a_local][h_local]
    __shared__ float h1s[64][33];
    __shared__ float w2s[HDIM];
    __shared__ float red[256];

    if (tid < HDIM) w2s[tid] = W2[tid];

    const float* h0g = &g_h[0][(size_t)n * LDIM * HDIM];
    const float* h1g = &g_h[1][(size_t)n * LDIM * HDIM];

    const int ay = ty * 4 + hp * 2;   // first of my 2 a-rows (local)
    const int by = tx * 4;            // first of my 4 b-rows (local)

    float acc = 0.f;

    for (int ch = 0; ch < 8; ch++) {
        __syncthreads();
        #pragma unroll
        for (int it = 0; it < 4; it++) {
            int idx = it * 512 + tid;          // 0..2047
            int al = idx >> 5, hl = idx & 31;
            h0s[al][hl] = h0g[(size_t)(qa * 64 + al) * HDIM + ch * 32 + hl];
            h1s[al][hl] = h1g[(size_t)(qb * 64 + al) * HDIM + ch * 32 + hl];
        }
        __syncthreads();

        #pragma unroll 8
        for (int hh = 0; hh < 32; hh++) {
            float A0 = h0s[ay + 0][hh];
            float A1 = h0s[ay + 1][hh];
            float B0 = h1s[by + 0][hh];
            float B1 = h1s[by + 1][hh];
            float B2v = h1s[by + 2][hh];
            float B3 = h1s[by + 3][hh];

            float s00 = fmaxf(A0 + B0, 0.f);
            float s01 = fmaxf(A0 + B1, 0.f);
            float s02 = fmaxf(A0 + B2v, 0.f);
            float s03 = fmaxf(A0 + B3, 0.f);
            float s10 = fmaxf(A1 + B0, 0.f);
            float s11 = fmaxf(A1 + B1, 0.f);
            float s12 = fmaxf(A1 + B2v, 0.f);
            float s13 = fmaxf(A1 + B3, 0.f);

            float s = ((s00 + s01) + (s02 + s03)) + ((s10 + s11) + (s12 + s13));
            acc = fmaf(w2s[ch * 32 + hh], s, acc);
        }
    }

    // Reduce the two u-halves
    if (hp == 1) red[t2] = acc;
    __syncthreads();
    if (hp == 0) {
        float total = acc + red[t2] + 16.0f * b2[0];
        const int I = qa * 16 + ty;
        const int J = qb * 16 + tx;
        out[n * 1024 + I * 32 + J] = total;
    }
}

// ---------------------------------------------------------------------------
// Kernel C: constant pairs tensor: pairs[n,p] = (p/32, p%32), as floats.
// ---------------------------------------------------------------------------
__global__ void pairs_kernel(float* __restrict__ out)
{
    int tid = blockIdx.x * blockDim.x + threadIdx.x;
    if (tid < 32 * 1024) {
        int p = tid & 1023;
        out[32768 + 2 * tid]     = (float)(p >> 5);
        out[32768 + 2 * tid + 1] = (float)(p & 31);
    }
}

extern "C" void kernel_launch(void* const* d_in, const int* in_sizes, int n_in,
                              void* d_out, int out_size)
{
    const float* fea  = (const float*)d_in[0];
    const int*   ind0 = (const int*)  d_in[1];
    const int*   ind1 = (const int*)  d_in[2];

    int base = 3;
    if (n_in >= 9 && in_sizes[3] == 1) base = 4;

    const float* W1a = (const float*)d_in[base + 0];
    const float* W1b = (const float*)d_in[base + 1];
    const float* b1  = (const float*)d_in[base + 2];
    const float* W2  = (const float*)d_in[base + 3];
    const float* b2  = (const float*)d_in[base + 4];

    float* out = (float*)d_out;

    gemm_kernel<<<dim3(8, 2, NUMB), 256>>>(fea, ind0, ind1, W1a, W1b, b1);
    if (out_size >= 98304) {
        pairs_kernel<<<128, 256>>>(out);
    }
    pair_kernel<<<dim3(4, NUMB), 512>>>(W2, b2, out);
}

// round 7
// speedup vs baseline: 1.3428x; 1.0498x over previous
#include <cuda_runtime.h>

#define NUMB 32
#define LDIM 128
#define DDIM 256
#define HDIM 256
#define BAG  300
#define POOL 1200

typedef unsigned long long ull;

__device__ __forceinline__ ull pack2(float x, float y) {
    ull r; asm("mov.b64 %0, {%1, %2};" : "=l"(r) : "f"(x), "f"(y)); return r;
}
__device__ __forceinline__ void unpack2(ull v, float &x, float &y) {
    asm("mov.b64 {%0, %1}, %2;" : "=f"(x), "=f"(y) : "l"(v));
}
__device__ __forceinline__ ull fma2(ull a, ull b, ull c) {
    ull d; asm("fma.rn.f32x2 %0, %1, %2, %3;" : "=l"(d) : "l"(a), "l"(b), "l"(c));
    return d;
}

// Hidden activations, natural layout: [side][n*128 + a][h]
__device__ float g_h[2][NUMB * LDIM * HDIM];

// ---------------------------------------------------------------------------
// Kernel A: gather + GEMM  h[side][n,a,:] = f[side][n,a,:] @ W1 (+ b1 if side)
// Packed-f32x2 version. Tile: 16 rows x 256 h-cols per block (256 threads).
// Thread: cx = tid&127 -> cols {2cx,2cx+1}; rh = tid>>7 -> 8 rows.
// Shared tile is TRANSPOSED: fs_t[d][row], stride 20 floats so every
// fs_t[d] row is 16B-aligned -> row-pairs load straight into packed regs
// via LDS.128 (2 packed operands per load), zero pack instructions on f.
// Inner loop per d: 2 LDS.128 + 2 w-dup packs + 8 FFMA2 (= 16 FMA lanes).
// ---------------------------------------------------------------------------
__global__ void __launch_bounds__(256, 3) gemm_kernel(
    const float* __restrict__ fea,
    const int*   __restrict__ ind0,
    const int*   __restrict__ ind1,
    const float* __restrict__ W1a,
    const float* __restrict__ W1b,
    const float* __restrict__ b1)
{
    const int rt   = blockIdx.x;   // row tile 0..7 (16 rows each)
    const int side = blockIdx.y;   // 0 or 1
    const int n    = blockIdx.z;   // 0..31
    const int tid  = threadIdx.x;
    const int cx   = tid & 127;    // h pair index -> cols 2cx, 2cx+1
    const int rh   = tid >> 7;     // row half (0/1)

    __shared__ __align__(16) float fs_t[DDIM][20];   // [d][row], 20 KB

    const int*   ind = side ? ind1 : ind0;
    const float* W1  = side ? W1b  : W1a;

    // Gather 16 feature rows; thread tid = feature dim d (coalesced LDG),
    // transposed STS (4-way conflict, amortized over the 256-step loop).
    #pragma unroll
    for (int r = 0; r < 16; r++) {
        int a   = rt * 16 + r;
        int top = a >> 2, c = a & 3;
        int id  = ind[(n * 32 + top) * 4 + c] + BAG * c;
        int row = (n * 2 + side) * POOL + id;
        fs_t[tid][r] = fea[(size_t)row * DDIM + tid];
    }
    __syncthreads();

    ull acc0[4], acc1[4];
    #pragma unroll
    for (int p = 0; p < 4; p++) { acc0[p] = 0ULL; acc1[p] = 0ULL; }

    const float* Wp = W1 + 2 * cx;
    const int r0 = rh * 8;

    #pragma unroll 2
    for (int d0 = 0; d0 < DDIM; d0 += 4) {
        float2 w[4];
        #pragma unroll
        for (int i = 0; i < 4; i++)
            w[i] = *(const float2*)(Wp + (size_t)(d0 + i) * HDIM);

        #pragma unroll
        for (int dd = 0; dd < 4; dd++) {
            ull wa = pack2(w[dd].x, w[dd].x);
            ull wb = pack2(w[dd].y, w[dd].y);
            const ulonglong2* fp =
                (const ulonglong2*)&fs_t[d0 + dd][r0];
            ulonglong2 fA = fp[0];   // rows r0+0..3 as 2 packed pairs
            ulonglong2 fB = fp[1];   // rows r0+4..7
            acc0[0] = fma2(fA.x, wa, acc0[0]);
            acc1[0] = fma2(fA.x, wb, acc1[0]);
            acc0[1] = fma2(fA.y, wa, acc0[1]);
            acc1[1] = fma2(fA.y, wb, acc1[1]);
            acc0[2] = fma2(fB.x, wa, acc0[2]);
            acc1[2] = fma2(fB.x, wb, acc1[2]);
            acc0[3] = fma2(fB.y, wa, acc0[3]);
            acc1[3] = fma2(fB.y, wb, acc1[3]);
        }
    }

    float2 bias = make_float2(0.f, 0.f);
    if (side) bias = *(const float2*)(b1 + 2 * cx);

    float* outp = &g_h[side][((size_t)(n * LDIM + rt * 16 + r0)) * HDIM + 2 * cx];
    #pragma unroll
    for (int p = 0; p < 4; p++) {
        float c0lo, c0hi, c1lo, c1hi;
        unpack2(acc0[p], c0lo, c0hi);
        unpack2(acc1[p], c1lo, c1hi);
        *(float2*)(outp + (size_t)(2 * p)     * HDIM) =
            make_float2(c0lo + bias.x, c1lo + bias.y);
        *(float2*)(outp + (size_t)(2 * p + 1) * HDIM) =
            make_float2(c0hi + bias.x, c1hi + bias.y);
    }
}

// ---------------------------------------------------------------------------
// Kernel B: pairwise relu-score + fused 4x4 patch sum. (unchanged)
// out[n,I,J] = sum_{u,v<4} sum_h relu(h0[n,4I+u,h]+h1[n,4J+v,h]) * W2[h] + 16 b2
// ---------------------------------------------------------------------------
__global__ void __launch_bounds__(512) pair_kernel(
    const float* __restrict__ W2,
    const float* __restrict__ b2,
    float*       __restrict__ out)
{
    const int n  = blockIdx.y;
    const int qa = blockIdx.x >> 1;
    const int qb = blockIdx.x & 1;
    const int tid = threadIdx.x;
    const int hp = tid >> 8;          // 0/1: which u-pair
    const int t2 = tid & 255;
    const int tx = t2 & 15;           // J patch within quadrant
    const int ty = t2 >> 4;           // I patch within quadrant

    __shared__ float h0s[64][33];     // [a_local][h_local]
    __shared__ float h1s[64][33];
    __shared__ float w2s[HDIM];
    __shared__ float red[256];

    if (tid < HDIM) w2s[tid] = W2[tid];

    const float* h0g = &g_h[0][(size_t)n * LDIM * HDIM];
    const float* h1g = &g_h[1][(size_t)n * LDIM * HDIM];

    const int ay = ty * 4 + hp * 2;   // first of my 2 a-rows (local)
    const int by = tx * 4;            // first of my 4 b-rows (local)

    float acc = 0.f;

    for (int ch = 0; ch < 8; ch++) {
        __syncthreads();
        #pragma unroll
        for (int it = 0; it < 4; it++) {
            int idx = it * 512 + tid;          // 0..2047
            int al = idx >> 5, hl = idx & 31;
            h0s[al][hl] = h0g[(size_t)(qa * 64 + al) * HDIM + ch * 32 + hl];
            h1s[al][hl] = h1g[(size_t)(qb * 64 + al) * HDIM + ch * 32 + hl];
        }
        __syncthreads();

        #pragma unroll 8
        for (int hh = 0; hh < 32; hh++) {
            float A0 = h0s[ay + 0][hh];
            float A1 = h0s[ay + 1][hh];
            float B0 = h1s[by + 0][hh];
            float B1 = h1s[by + 1][hh];
            float B2v = h1s[by + 2][hh];
            float B3 = h1s[by + 3][hh];

            float s00 = fmaxf(A0 + B0, 0.f);
            float s01 = fmaxf(A0 + B1, 0.f);
            float s02 = fmaxf(A0 + B2v, 0.f);
            float s03 = fmaxf(A0 + B3, 0.f);
            float s10 = fmaxf(A1 + B0, 0.f);
            float s11 = fmaxf(A1 + B1, 0.f);
            float s12 = fmaxf(A1 + B2v, 0.f);
            float s13 = fmaxf(A1 + B3, 0.f);

            float s = ((s00 + s01) + (s02 + s03)) + ((s10 + s11) + (s12 + s13));
            acc = fmaf(w2s[ch * 32 + hh], s, acc);
        }
    }

    if (hp == 1) red[t2] = acc;
    __syncthreads();
    if (hp == 0) {
        float total = acc + red[t2] + 16.0f * b2[0];
        const int I = qa * 16 + ty;
        const int J = qb * 16 + tx;
        out[n * 1024 + I * 32 + J] = total;
    }
}

// ---------------------------------------------------------------------------
// Kernel C: constant pairs tensor: pairs[n,p] = (p/32, p%32), as floats.
// ---------------------------------------------------------------------------
__global__ void pairs_kernel(float* __restrict__ out)
{
    int tid = blockIdx.x * blockDim.x + threadIdx.x;
    if (tid < 32 * 1024) {
        int p = tid & 1023;
        out[32768 + 2 * tid]     = (float)(p >> 5);
        out[32768 + 2 * tid + 1] = (float)(p & 31);
    }
}

extern "C" void kernel_launch(void* const* d_in, const int* in_sizes, int n_in,
                              void* d_out, int out_size)
{
    const float* fea  = (const float*)d_in[0];
    const int*   ind0 = (const int*)  d_in[1];
    const int*   ind1 = (const int*)  d_in[2];

    int base = 3;
    if (n_in >= 9 && in_sizes[3] == 1) base = 4;

    const float* W1a = (const float*)d_in[base + 0];
    const float* W1b = (const float*)d_in[base + 1];
    const float* b1  = (const float*)d_in[base + 2];
    const float* W2  = (const float*)d_in[base + 3];
    const float* b2  = (const float*)d_in[base + 4];

    float* out = (float*)d_out;

    gemm_kernel<<<dim3(8, 2, NUMB), 256>>>(fea, ind0, ind1, W1a, W1b, b1);
    if (out_size >= 98304) {
        pairs_kernel<<<128, 256>>>(out);
    }
    pair_kernel<<<dim3(4, NUMB), 512>>>(W2, b2, out);
}

// round 12
// speedup vs baseline: 1.8790x; 1.3993x over previous
#include <cuda_runtime.h>
#include <cuda_bf16.h>
#include <cstdint>

#define NUMB 32
#define LDIM 128
#define DDIM 256
#define HDIM 256
#define BAG  300
#define POOL 1200

// ---------------------------------------------------------------------------
// helpers
// ---------------------------------------------------------------------------
__device__ __forceinline__ uint32_t smem_u32(const void* p) {
    uint32_t a;
    asm("{ .reg .u64 t; cvta.to.shared.u64 t, %1; cvt.u32.u64 %0, t; }"
        : "=r"(a) : "l"(p));
    return a;
}

// pack two fp32 -> bf16x2 (lo -> bits[15:0], hi -> bits[31:16])
__device__ __forceinline__ uint32_t bfpack(float lo, float hi) {
    uint32_t r;
    asm("cvt.rn.bf16x2.f32 %0, %1, %2;" : "=r"(r) : "f"(hi), "f"(lo));
    return r;
}

#define LDSM4(R, ADDR)                                                        \
    asm volatile("ldmatrix.sync.aligned.m8n8.x4.shared.b16 {%0,%1,%2,%3}, [%4];" \
        : "=r"((R)[0]), "=r"((R)[1]), "=r"((R)[2]), "=r"((R)[3]) : "r"(ADDR))

#define MMA_BF16(C, A, B0, B1)                                                \
    asm volatile("mma.sync.aligned.m16n8k16.row.col.f32.bf16.bf16.f32 "       \
        "{%0,%1,%2,%3}, {%4,%5,%6,%7}, {%8,%9}, {%0,%1,%2,%3};"               \
        : "+f"((C)[0]), "+f"((C)[1]), "+f"((C)[2]), "+f"((C)[3])              \
        : "r"((A)[0]), "r"((A)[1]), "r"((A)[2]), "r"((A)[3]),                 \
          "r"(B0), "r"(B1))

// ---------------------------------------------------------------------------
// Global scratch
// ---------------------------------------------------------------------------
__device__ float g_h[2][NUMB * LDIM * HDIM];                 // [side][n*128+a][h]
__device__ __nv_bfloat16 g_w1t[2][2][HDIM * DDIM];           // [side][hi/lo][h][d]

// ---------------------------------------------------------------------------
// Kernel T: transpose + bf16-split W1 ([d][h] -> [h][d], hi/lo)
// ---------------------------------------------------------------------------
__global__ void __launch_bounds__(256) w1t_kernel(
    const float* __restrict__ W1a, const float* __restrict__ W1b)
{
    const int s = blockIdx.z;
    const float* W1 = s ? W1b : W1a;
    __shared__ float t[32][33];
    const int tx = threadIdx.x, ty = threadIdx.y;   // (32, 8)
    const int hb = blockIdx.x * 32, db = blockIdx.y * 32;

    #pragma unroll
    for (int i = 0; i < 4; i++)
        t[ty + i * 8][tx] = W1[(size_t)(db + ty + i * 8) * HDIM + hb + tx];
    __syncthreads();
    #pragma unroll
    for (int i = 0; i < 4; i++) {
        int h = hb + ty + i * 8, d = db + tx;
        float v  = t[tx][ty + i * 8];
        __nv_bfloat16 hb16 = __float2bfloat16(v);
        float lo = v - __bfloat162float(hb16);
        g_w1t[s][0][(size_t)h * DDIM + d] = hb16;
        g_w1t[s][1][(size_t)h * DDIM + d] = __float2bfloat16(lo);
    }
}

// ---------------------------------------------------------------------------
// Kernel A: gather + split-bf16 mma.sync GEMM.
// CTA = (nh, side, n): C[128a x 128h] = F[128 x 256d] * W1T[128h x 256d]^T
// K chunks of 64; smem tiles [128 rows][64 bf16] padded to 144B row stride.
// 8 warps, warp tile 64x32 (wm = w&1, wn = w>>2... wn = w>>1).
// 3 MMA passes (hi*hi + hi*lo + lo*hi) per fragment pair.
// Epilogue: C -> g_h[side][n*128+a][h] (+ b1 on side 1).
// ---------------------------------------------------------------------------
__global__ void __launch_bounds__(256, 1) gemm_kernel(
    const float* __restrict__ fea,
    const int*   __restrict__ ind0,
    const int*   __restrict__ ind1,
    const float* __restrict__ b1)
{
    extern __shared__ char dyn[];
    // tiles: aHi, aLo, wHi, wLo : 128 * 144 bytes each
    char* aHi = dyn;
    char* aLo = dyn + 18432;
    char* wHi = dyn + 36864;
    char* wLo = dyn + 55296;

    __shared__ float b1s[128];

    const int nh   = blockIdx.x;
    const int side = blockIdx.y;
    const int n    = blockIdx.z;
    const int tid  = threadIdx.x;
    const int wid  = tid >> 5;
    const int lane = tid & 31;
    const int wm   = wid & 1;      // m block: wm*64
    const int wn   = wid >> 1;     // n block: wn*32

    if (tid < 128) b1s[tid] = b1[nh * 128 + tid];

    // Gathered A row pointers (fixed per thread; 8 slots)
    const int* ind = side ? ind1 : ind0;
    const float* asrc[8];
    #pragma unroll
    for (int p = 0; p < 8; p++) {
        int idx = p * 256 + tid;
        int r   = idx >> 4;          // 0..127
        int d4  = (idx & 15) * 4;
        int top = r >> 2, cc = r & 3;
        int id  = ind[(n * 32 + top) * 4 + cc] + BAG * cc;
        int frw = (n * 2 + side) * POOL + id;
        asrc[p] = fea + (size_t)frw * DDIM + d4;
    }
    const __nv_bfloat16* wbaseH = &g_w1t[side][0][(size_t)nh * 128 * DDIM];
    const __nv_bfloat16* wbaseL = &g_w1t[side][1][(size_t)nh * 128 * DDIM];

    float c[4][4][4];
    #pragma unroll
    for (int mt = 0; mt < 4; mt++)
        #pragma unroll
        for (int nt = 0; nt < 4; nt++)
            #pragma unroll
            for (int q = 0; q < 4; q++) c[mt][nt][q] = 0.f;

    const uint32_t uaHi = smem_u32(aHi), uaLo = smem_u32(aLo);
    const uint32_t uwHi = smem_u32(wHi), uwLo = smem_u32(wLo);

    // ldmatrix base byte-offsets (within a tile)
    const uint32_t aOff = (uint32_t)(wm * 64 + (lane & 15)) * 144 + (lane >> 4) * 16;
    const uint32_t bOff = (uint32_t)(wn * 32 + (lane & 7) + ((lane >> 4) << 3)) * 144
                        + ((lane >> 3) & 1) * 16;

    for (int ck = 0; ck < 4; ck++) {
        if (ck) __syncthreads();   // protect smem reuse

        // ---- fill tiles ----
        #pragma unroll
        for (int p = 0; p < 8; p++) {
            int idx = p * 256 + tid;
            int r   = idx >> 4;
            int d4  = (idx & 15) * 4;
            uint32_t so = (uint32_t)r * 144 + d4 * 2;

            float4 f = *(const float4*)(asrc[p] + ck * 64);
            uint32_t h0 = bfpack(f.x, f.y);
            uint32_t h1 = bfpack(f.z, f.w);
            float hx = __uint_as_float(h0 << 16);
            float hy = __uint_as_float(h0 & 0xFFFF0000u);
            float hz = __uint_as_float(h1 << 16);
            float hw = __uint_as_float(h1 & 0xFFFF0000u);
            uint32_t l0 = bfpack(f.x - hx, f.y - hy);
            uint32_t l1 = bfpack(f.z - hz, f.w - hw);
            *(uint2*)(aHi + so) = make_uint2(h0, h1);
            *(uint2*)(aLo + so) = make_uint2(l0, l1);

            size_t woff = (size_t)r * DDIM + ck * 64 + d4;
            *(uint2*)(wHi + so) = *(const uint2*)(wbaseH + woff);
            *(uint2*)(wLo + so) = *(const uint2*)(wbaseL + woff);
        }
        __syncthreads();

        // ---- 4 k16-steps ----
        #pragma unroll
        for (int ks = 0; ks < 4; ks++) {
            uint32_t ah[4][4], al[4][4], bh[2][4], bl[2][4];
            #pragma unroll
            for (int mt = 0; mt < 4; mt++) {
                uint32_t ao = aOff + (uint32_t)mt * (16 * 144) + ks * 32;
                LDSM4(ah[mt], uaHi + ao);
                LDSM4(al[mt], uaLo + ao);
            }
            #pragma unroll
            for (int nt2 = 0; nt2 < 2; nt2++) {
                uint32_t bo = bOff + (uint32_t)nt2 * (16 * 144) + ks * 32;
                LDSM4(bh[nt2], uwHi + bo);
                LDSM4(bl[nt2], uwLo + bo);
            }
            #pragma unroll
            for (int mt = 0; mt < 4; mt++) {
                #pragma unroll
                for (int nt = 0; nt < 4; nt++) {
                    int n2 = nt >> 1, s2 = (nt & 1) * 2;
                    MMA_BF16(c[mt][nt], ah[mt], bh[n2][s2], bh[n2][s2 + 1]);
                    MMA_BF16(c[mt][nt], ah[mt], bl[n2][s2], bl[n2][s2 + 1]);
                    MMA_BF16(c[mt][nt], al[mt], bh[n2][s2], bh[n2][s2 + 1]);
                }
            }
        }
    }

    // ---- epilogue ----
    const float bsel = side ? 1.0f : 0.0f;
    #pragma unroll
    for (int mt = 0; mt < 4; mt++) {
        #pragma unroll
        for (int nt = 0; nt < 4; nt++) {
            int a0 = wm * 64 + mt * 16 + (lane >> 2);
            int cl = wn * 32 + nt * 8 + (lane & 3) * 2;
            float bx = bsel * b1s[cl], by = bsel * b1s[cl + 1];
            float* dst0 = &g_h[side][((size_t)(n * LDIM + a0)) * HDIM + nh * 128 + cl];
            *(float2*)dst0 = make_float2(c[mt][nt][0] + bx, c[mt][nt][1] + by);
            float* dst1 = dst0 + (size_t)8 * HDIM;
            *(float2*)dst1 = make_float2(c[mt][nt][2] + bx, c[mt][nt][3] + by);
        }
    }
}

// ---------------------------------------------------------------------------
// Kernel B: pairwise relu-score + fused 4x4 patch sum ([a][h] layout).
// ---------------------------------------------------------------------------
__global__ void __launch_bounds__(512) pair_kernel(
    const float* __restrict__ W2,
    const float* __restrict__ b2,
    float*       __restrict__ out)
{
    const int n  = blockIdx.y;
    const int qa = blockIdx.x >> 1;
    const int qb = blockIdx.x & 1;
    const int tid = threadIdx.x;
    const int hp = tid >> 8;
    const int t2 = tid & 255;
    const int tx = t2 & 15;
    const int ty = t2 >> 4;

    __shared__ float h0s[64][33];
    __shared__ float h1s[64][33];
    __shared__ float w2s[HDIM];
    __shared__ float red[256];

    if (tid < HDIM) w2s[tid] = W2[tid];

    const float* h0g = &g_h[0][(size_t)n * LDIM * HDIM];
    const float* h1g = &g_h[1][(size_t)n * LDIM * HDIM];

    const int ay = ty * 4 + hp * 2;
    const int by = tx * 4;

    float acc = 0.f;

    for (int ch = 0; ch < 8; ch++) {
        __syncthreads();
        #pragma unroll
        for (int it = 0; it < 4; it++) {
            int idx = it * 512 + tid;
            int al = idx >> 5, hl = idx & 31;
            h0s[al][hl] = h0g[(size_t)(qa * 64 + al) * HDIM + ch * 32 + hl];
            h1s[al][hl] = h1g[(size_t)(qb * 64 + al) * HDIM + ch * 32 + hl];
        }
        __syncthreads();

        #pragma unroll 8
        for (int hh = 0; hh < 32; hh++) {
            float A0 = h0s[ay + 0][hh];
            float A1 = h0s[ay + 1][hh];
            float B0 = h1s[by + 0][hh];
            float B1 = h1s[by + 1][hh];
            float B2v = h1s[by + 2][hh];
            float B3 = h1s[by + 3][hh];

            float s00 = fmaxf(A0 + B0, 0.f);
            float s01 = fmaxf(A0 + B1, 0.f);
            float s02 = fmaxf(A0 + B2v, 0.f);
            float s03 = fmaxf(A0 + B3, 0.f);
            float s10 = fmaxf(A1 + B0, 0.f);
            float s11 = fmaxf(A1 + B1, 0.f);
            float s12 = fmaxf(A1 + B2v, 0.f);
            float s13 = fmaxf(A1 + B3, 0.f);

            float s = ((s00 + s01) + (s02 + s03)) + ((s10 + s11) + (s12 + s13));
            acc = fmaf(w2s[ch * 32 + hh], s, acc);
        }
    }

    if (hp == 1) red[t2] = acc;
    __syncthreads();
    if (hp == 0) {
        float total = acc + red[t2] + 16.0f * b2[0];
        const int I = qa * 16 + ty;
        const int J = qb * 16 + tx;
        out[n * 1024 + I * 32 + J] = total;
    }
}

// ---------------------------------------------------------------------------
// Kernel C: constant pairs tensor
// ---------------------------------------------------------------------------
__global__ void pairs_kernel(float* __restrict__ out)
{
    int tid = blockIdx.x * blockDim.x + threadIdx.x;
    if (tid < 32 * 1024) {
        int p = tid & 1023;
        out[32768 + 2 * tid]     = (float)(p >> 5);
        out[32768 + 2 * tid + 1] = (float)(p & 31);
    }
}

extern "C" void kernel_launch(void* const* d_in, const int* in_sizes, int n_in,
                              void* d_out, int out_size)
{
    const float* fea  = (const float*)d_in[0];
    const int*   ind0 = (const int*)  d_in[1];
    const int*   ind1 = (const int*)  d_in[2];

    int base = 3;
    if (n_in >= 9 && in_sizes[3] == 1) base = 4;

    const float* W1a = (const float*)d_in[base + 0];
    const float* W1b = (const float*)d_in[base + 1];
    const float* b1  = (const float*)d_in[base + 2];
    const float* W2  = (const float*)d_in[base + 3];
    const float* b2  = (const float*)d_in[base + 4];

    float* out = (float*)d_out;

    const int dyn_bytes = 4 * 128 * 144;   // 73728
    cudaFuncSetAttribute(gemm_kernel, cudaFuncAttributeMaxDynamicSharedMemorySize,
                         dyn_bytes);

    w1t_kernel<<<dim3(8, 8, 2), dim3(32, 8)>>>(W1a, W1b);
    gemm_kernel<<<dim3(2, 2, NUMB), 256, dyn_bytes>>>(fea, ind0, ind1, b1);
    if (out_size >= 98304) {
        pairs_kernel<<<128, 256>>>(out);
    }
    pair_kernel<<<dim3(4, NUMB), 512>>>(W2, b2, out);
}

// round 16
// speedup vs baseline: 2.1290x; 1.1331x over previous
#include <cuda_runtime.h>
#include <cuda_bf16.h>
#include <cstdint>

#define NUMB 32
#define LDIM 128
#define DDIM 256
#define HDIM 256
#define BAG  300
#define POOL 1200

// ---------------------------------------------------------------------------
// helpers
// ---------------------------------------------------------------------------
__device__ __forceinline__ uint32_t smem_u32(const void* p) {
    uint32_t a;
    asm("{ .reg .u64 t; cvta.to.shared.u64 t, %1; cvt.u32.u64 %0, t; }"
        : "=r"(a) : "l"(p));
    return a;
}
__device__ __forceinline__ uint32_t bfpack(float lo, float hi) {
    uint32_t r;
    asm("cvt.rn.bf16x2.f32 %0, %1, %2;" : "=r"(r) : "f"(hi), "f"(lo));
    return r;
}
#define LDSM4(R, ADDR)                                                        \
    asm volatile("ldmatrix.sync.aligned.m8n8.x4.shared.b16 {%0,%1,%2,%3}, [%4];" \
        : "=r"((R)[0]), "=r"((R)[1]), "=r"((R)[2]), "=r"((R)[3]) : "r"(ADDR))
#define MMA_BF16(C, A, B0, B1)                                                \
    asm volatile("mma.sync.aligned.m16n8k16.row.col.f32.bf16.bf16.f32 "       \
        "{%0,%1,%2,%3}, {%4,%5,%6,%7}, {%8,%9}, {%0,%1,%2,%3};"               \
        : "+f"((C)[0]), "+f"((C)[1]), "+f"((C)[2]), "+f"((C)[3])              \
        : "r"((A)[0]), "r"((A)[1]), "r"((A)[2]), "r"((A)[3]),                 \
          "r"(B0), "r"(B1))

// ---------------------------------------------------------------------------
// Global scratch
// ---------------------------------------------------------------------------
__device__ float g_hT[2][NUMB * HDIM * LDIM];                // [side][n][h][a]
__device__ __nv_bfloat16 g_w1t[2][2][HDIM * DDIM];           // [side][hi/lo][h][d]
__device__ float g_part[4][NUMB * 1024];                     // [hs][n*1024 + I*32 + J]

// ---------------------------------------------------------------------------
// Kernel T: transpose + bf16-split W1 ([d][h] -> [h][d], hi/lo)
// ---------------------------------------------------------------------------
__global__ void __launch_bounds__(256) w1t_kernel(
    const float* __restrict__ W1a, const float* __restrict__ W1b)
{
    const int s = blockIdx.z;
    const float* W1 = s ? W1b : W1a;
    __shared__ float t[32][33];
    const int tx = threadIdx.x, ty = threadIdx.y;   // (32, 8)
    const int hb = blockIdx.x * 32, db = blockIdx.y * 32;

    #pragma unroll
    for (int i = 0; i < 4; i++)
        t[ty + i * 8][tx] = W1[(size_t)(db + ty + i * 8) * HDIM + hb + tx];
    __syncthreads();
    #pragma unroll
    for (int i = 0; i < 4; i++) {
        int h = hb + ty + i * 8, d = db + tx;
        float v  = t[tx][ty + i * 8];
        __nv_bfloat16 hb16 = __float2bfloat16(v);
        float lo = v - __bfloat162float(hb16);
        g_w1t[s][0][(size_t)h * DDIM + d] = hb16;
        g_w1t[s][1][(size_t)h * DDIM + d] = __float2bfloat16(lo);
    }
}

// ---------------------------------------------------------------------------
// Kernel A: gather + split-bf16 mma.sync GEMM. (epilogue now writes [h][a])
// ---------------------------------------------------------------------------
__global__ void __launch_bounds__(256, 1) gemm_kernel(
    const float* __restrict__ fea,
    const int*   __restrict__ ind0,
    const int*   __restrict__ ind1,
    const float* __restrict__ b1)
{
    extern __shared__ char dyn[];
    char* aHi = dyn;
    char* aLo = dyn + 18432;
    char* wHi = dyn + 36864;
    char* wLo = dyn + 55296;

    __shared__ float b1s[128];

    const int nh   = blockIdx.x;
    const int side = blockIdx.y;
    const int n    = blockIdx.z;
    const int tid  = threadIdx.x;
    const int wid  = tid >> 5;
    const int lane = tid & 31;
    const int wm   = wid & 1;
    const int wn   = wid >> 1;

    if (tid < 128) b1s[tid] = b1[nh * 128 + tid];

    const int* ind = side ? ind1 : ind0;
    const float* asrc[8];
    #pragma unroll
    for (int p = 0; p < 8; p++) {
        int idx = p * 256 + tid;
        int r   = idx >> 4;
        int d4  = (idx & 15) * 4;
        int top = r >> 2, cc = r & 3;
        int id  = ind[(n * 32 + top) * 4 + cc] + BAG * cc;
        int frw = (n * 2 + side) * POOL + id;
        asrc[p] = fea + (size_t)frw * DDIM + d4;
    }
    const __nv_bfloat16* wbaseH = &g_w1t[side][0][(size_t)nh * 128 * DDIM];
    const __nv_bfloat16* wbaseL = &g_w1t[side][1][(size_t)nh * 128 * DDIM];

    float c[4][4][4];
    #pragma unroll
    for (int mt = 0; mt < 4; mt++)
        #pragma unroll
        for (int nt = 0; nt < 4; nt++)
            #pragma unroll
            for (int q = 0; q < 4; q++) c[mt][nt][q] = 0.f;

    const uint32_t uaHi = smem_u32(aHi), uaLo = smem_u32(aLo);
    const uint32_t uwHi = smem_u32(wHi), uwLo = smem_u32(wLo);

    const uint32_t aOff = (uint32_t)(wm * 64 + (lane & 15)) * 144 + (lane >> 4) * 16;
    const uint32_t bOff = (uint32_t)(wn * 32 + (lane & 7) + ((lane >> 4) << 3)) * 144
                        + ((lane >> 3) & 1) * 16;

    for (int ck = 0; ck < 4; ck++) {
        if (ck) __syncthreads();

        #pragma unroll
        for (int p = 0; p < 8; p++) {
            int idx = p * 256 + tid;
            int r   = idx >> 4;
            int d4  = (idx & 15) * 4;
            uint32_t so = (uint32_t)r * 144 + d4 * 2;

            float4 f = *(const float4*)(asrc[p] + ck * 64);
            uint32_t h0 = bfpack(f.x, f.y);
            uint32_t h1 = bfpack(f.z, f.w);
            float hx = __uint_as_float(h0 << 16);
            float hy = __uint_as_float(h0 & 0xFFFF0000u);
            float hz = __uint_as_float(h1 << 16);
            float hw = __uint_as_float(h1 & 0xFFFF0000u);
            uint32_t l0 = bfpack(f.x - hx, f.y - hy);
            uint32_t l1 = bfpack(f.z - hz, f.w - hw);
            *(uint2*)(aHi + so) = make_uint2(h0, h1);
            *(uint2*)(aLo + so) = make_uint2(l0, l1);

            size_t woff = (size_t)r * DDIM + ck * 64 + d4;
            *(uint2*)(wHi + so) = *(const uint2*)(wbaseH + woff);
            *(uint2*)(wLo + so) = *(const uint2*)(wbaseL + woff);
        }
        __syncthreads();

        #pragma unroll
        for (int ks = 0; ks < 4; ks++) {
            uint32_t ah[4][4], al[4][4], bh[2][4], bl[2][4];
            #pragma unroll
            for (int mt = 0; mt < 4; mt++) {
                uint32_t ao = aOff + (uint32_t)mt * (16 * 144) + ks * 32;
                LDSM4(ah[mt], uaHi + ao);
                LDSM4(al[mt], uaLo + ao);
            }
            #pragma unroll
            for (int nt2 = 0; nt2 < 2; nt2++) {
                uint32_t bo = bOff + (uint32_t)nt2 * (16 * 144) + ks * 32;
                LDSM4(bh[nt2], uwHi + bo);
                LDSM4(bl[nt2], uwLo + bo);
            }
            #pragma unroll
            for (int mt = 0; mt < 4; mt++) {
                #pragma unroll
                for (int nt = 0; nt < 4; nt++) {
                    int n2 = nt >> 1, s2 = (nt & 1) * 2;
                    MMA_BF16(c[mt][nt], ah[mt], bh[n2][s2], bh[n2][s2 + 1]);
                    MMA_BF16(c[mt][nt], ah[mt], bl[n2][s2], bl[n2][s2 + 1]);
                    MMA_BF16(c[mt][nt], al[mt], bh[n2][s2], bh[n2][s2 + 1]);
                }
            }
        }
    }

    // ---- epilogue: write TRANSPOSED g_hT[side][n][h][a] ----
    const float bsel = side ? 1.0f : 0.0f;
    #pragma unroll
    for (int mt = 0; mt < 4; mt++) {
        #pragma unroll
        for (int nt = 0; nt < 4; nt++) {
            int a0 = wm * 64 + mt * 16 + (lane >> 2);
            int cl = wn * 32 + nt * 8 + (lane & 3) * 2;
            float bx = bsel * b1s[cl], by = bsel * b1s[cl + 1];
            float* base = &g_hT[side][((size_t)(n * HDIM + nh * 128 + cl)) * LDIM + a0];
            base[0]            = c[mt][nt][0] + bx;
            base[LDIM]         = c[mt][nt][1] + by;
            base[8]            = c[mt][nt][2] + bx;
            base[LDIM + 8]     = c[mt][nt][3] + by;
        }
    }
}

// ---------------------------------------------------------------------------
// Kernel B: pairwise relu-score + fused 4x4 patch sum, H-split x4.
// Block = (hs, qa, qb, n): 64 h-slice, 64x64 pair tile; 256 threads,
// each thread one (I,J) patch = 4a x 4b via 2 LDS.128 per h.
// Writes partial sums to g_part[hs].
// ---------------------------------------------------------------------------
__global__ void __launch_bounds__(256) pair_kernel(const float* __restrict__ W2)
{
    const int n  = blockIdx.y;
    const int hs = blockIdx.x >> 2;
    const int qa = (blockIdx.x >> 1) & 1;
    const int qb = blockIdx.x & 1;
    const int tx = threadIdx.x & 15;
    const int ty = threadIdx.x >> 4;

    __shared__ float h0s[64][64];
    __shared__ float h1s[64][64];
    __shared__ float w2s[64];

    if (threadIdx.x < 64) w2s[threadIdx.x] = W2[hs * 64 + threadIdx.x];

    const float* h0g = &g_hT[0][((size_t)n * HDIM + hs * 64) * LDIM + qa * 64];
    const float* h1g = &g_hT[1][((size_t)n * HDIM + hs * 64) * LDIM + qb * 64];

    #pragma unroll
    for (int i = 0; i < 16; i++) {
        int idx = i * 256 + threadIdx.x;
        int hl = idx >> 6, al = idx & 63;
        h0s[hl][al] = h0g[(size_t)hl * LDIM + al];
        h1s[hl][al] = h1g[(size_t)hl * LDIM + al];
    }
    __syncthreads();

    float acc = 0.f;
    #pragma unroll 8
    for (int hh = 0; hh < 64; hh++) {
        float4 a4 = *(const float4*)&h0s[hh][ty * 4];
        float4 b4 = *(const float4*)&h1s[hh][tx * 4];
        float A[4] = {a4.x, a4.y, a4.z, a4.w};
        float B[4] = {b4.x, b4.y, b4.z, b4.w};
        float s = 0.f;
        #pragma unroll
        for (int u = 0; u < 4; u++)
            #pragma unroll
            for (int v = 0; v < 4; v++)
                s += fmaxf(A[u] + B[v], 0.f);
        acc = fmaf(w2s[hh], s, acc);
    }

    const int I = qa * 16 + ty;
    const int J = qb * 16 + tx;
    g_part[hs][n * 1024 + I * 32 + J] = acc;
}

// ---------------------------------------------------------------------------
// Kernel R: deterministic reduce of the 4 H-partials + bias.
// ---------------------------------------------------------------------------
__global__ void __launch_bounds__(256) reduce_kernel(
    const float* __restrict__ b2, float* __restrict__ out)
{
    int i = blockIdx.x * 256 + threadIdx.x;   // 0..32767
    out[i] = (g_part[0][i] + g_part[1][i]) + (g_part[2][i] + g_part[3][i])
           + 16.0f * b2[0];
}

// ---------------------------------------------------------------------------
// Kernel C: constant pairs tensor
// ---------------------------------------------------------------------------
__global__ void pairs_kernel(float* __restrict__ out)
{
    int tid = blockIdx.x * blockDim.x + threadIdx.x;
    if (tid < 32 * 1024) {
        int p = tid & 1023;
        out[32768 + 2 * tid]     = (float)(p >> 5);
        out[32768 + 2 * tid + 1] = (float)(p & 31);
    }
}

extern "C" void kernel_launch(void* const* d_in, const int* in_sizes, int n_in,
                              void* d_out, int out_size)
{
    const float* fea  = (const float*)d_in[0];
    const int*   ind0 = (const int*)  d_in[1];
    const int*   ind1 = (const int*)  d_in[2];

    int base = 3;
    if (n_in >= 9 && in_sizes[3] == 1) base = 4;

    const float* W1a = (const float*)d_in[base + 0];
    const float* W1b = (const float*)d_in[base + 1];
    const float* b1  = (const float*)d_in[base + 2];
    const float* W2  = (const float*)d_in[base + 3];
    const float* b2  = (const float*)d_in[base + 4];

    float* out = (float*)d_out;

    const int dyn_bytes = 4 * 128 * 144;   // 73728
    cudaFuncSetAttribute(gemm_kernel, cudaFuncAttributeMaxDynamicSharedMemorySize,
                         dyn_bytes);

    w1t_kernel<<<dim3(8, 8, 2), dim3(32, 8)>>>(W1a, W1b);
    gemm_kernel<<<dim3(2, 2, NUMB), 256, dyn_bytes>>>(fea, ind0, ind1, b1);
    if (out_size >= 98304) {
        pairs_kernel<<<128, 256>>>(out);
    }
    pair_kernel<<<dim3(16, NUMB), 256>>>(W2);
    reduce_kernel<<<128, 256>>>(b2, out);
}

// round 17
// speedup vs baseline: 2.3935x; 1.1242x over previous
#include <cuda_runtime.h>
#include <cuda_bf16.h>
#include <cstdint>

#define NUMB 32
#define LDIM 128
#define DDIM 256
#define HDIM 256
#define BAG  300
#define POOL 1200

// ---------------------------------------------------------------------------
// helpers
// ---------------------------------------------------------------------------
__device__ __forceinline__ uint32_t smem_u32(const void* p) {
    uint32_t a;
    asm("{ .reg .u64 t; cvta.to.shared.u64 t, %1; cvt.u32.u64 %0, t; }"
        : "=r"(a) : "l"(p));
    return a;
}
__device__ __forceinline__ uint32_t bfpack(float lo, float hi) {
    uint32_t r;
    asm("cvt.rn.bf16x2.f32 %0, %1, %2;" : "=r"(r) : "f"(hi), "f"(lo));
    return r;
}
#define LDSM4(R, ADDR)                                                        \
    asm volatile("ldmatrix.sync.aligned.m8n8.x4.shared.b16 {%0,%1,%2,%3}, [%4];" \
        : "=r"((R)[0]), "=r"((R)[1]), "=r"((R)[2]), "=r"((R)[3]) : "r"(ADDR))
#define MMA_BF16(C, A, B0, B1)                                                \
    asm volatile("mma.sync.aligned.m16n8k16.row.col.f32.bf16.bf16.f32 "       \
        "{%0,%1,%2,%3}, {%4,%5,%6,%7}, {%8,%9}, {%0,%1,%2,%3};"               \
        : "+f"((C)[0]), "+f"((C)[1]), "+f"((C)[2]), "+f"((C)[3])              \
        : "r"((A)[0]), "r"((A)[1]), "r"((A)[2]), "r"((A)[3]),                 \
          "r"(B0), "r"(B1))

// ---------------------------------------------------------------------------
// Global scratch
// ---------------------------------------------------------------------------
__device__ float g_hT[2][NUMB * HDIM * LDIM];                // [side][n][h][a]
__device__ __nv_bfloat16 g_w1t[2][2][HDIM * DDIM];           // [side][hi/lo][h][d]
__device__ float g_part[8][NUMB * 1024];                     // [hs][n*1024 + I*32 + J]

// ---------------------------------------------------------------------------
// Kernel T: transpose + bf16-split W1 ([d][h] -> [h][d], hi/lo)
// ---------------------------------------------------------------------------
__global__ void __launch_bounds__(256) w1t_kernel(
    const float* __restrict__ W1a, const float* __restrict__ W1b)
{
    const int s = blockIdx.z;
    const float* W1 = s ? W1b : W1a;
    __shared__ float t[32][33];
    const int tx = threadIdx.x, ty = threadIdx.y;   // (32, 8)
    const int hb = blockIdx.x * 32, db = blockIdx.y * 32;

    #pragma unroll
    for (int i = 0; i < 4; i++)
        t[ty + i * 8][tx] = W1[(size_t)(db + ty + i * 8) * HDIM + hb + tx];
    __syncthreads();
    #pragma unroll
    for (int i = 0; i < 4; i++) {
        int h = hb + ty + i * 8, d = db + tx;
        float v  = t[tx][ty + i * 8];
        __nv_bfloat16 hb16 = __float2bfloat16(v);
        float lo = v - __bfloat162float(hb16);
        g_w1t[s][0][(size_t)h * DDIM + d] = hb16;
        g_w1t[s][1][(size_t)h * DDIM + d] = __float2bfloat16(lo);
    }
}

// ---------------------------------------------------------------------------
// Kernel A: gather + split-bf16 mma.sync GEMM (epilogue writes [h][a])
// ---------------------------------------------------------------------------
__global__ void __launch_bounds__(256, 1) gemm_kernel(
    const float* __restrict__ fea,
    const int*   __restrict__ ind0,
    const int*   __restrict__ ind1,
    const float* __restrict__ b1)
{
    extern __shared__ char dyn[];
    char* aHi = dyn;
    char* aLo = dyn + 18432;
    char* wHi = dyn + 36864;
    char* wLo = dyn + 55296;

    __shared__ float b1s[128];

    const int nh   = blockIdx.x;
    const int side = blockIdx.y;
    const int n    = blockIdx.z;
    const int tid  = threadIdx.x;
    const int wid  = tid >> 5;
    const int lane = tid & 31;
    const int wm   = wid & 1;
    const int wn   = wid >> 1;

    if (tid < 128) b1s[tid] = b1[nh * 128 + tid];

    const int* ind = side ? ind1 : ind0;
    const float* asrc[8];
    #pragma unroll
    for (int p = 0; p < 8; p++) {
        int idx = p * 256 + tid;
        int r   = idx >> 4;
        int d4  = (idx & 15) * 4;
        int top = r >> 2, cc = r & 3;
        int id  = ind[(n * 32 + top) * 4 + cc] + BAG * cc;
        int frw = (n * 2 + side) * POOL + id;
        asrc[p] = fea + (size_t)frw * DDIM + d4;
    }
    const __nv_bfloat16* wbaseH = &g_w1t[side][0][(size_t)nh * 128 * DDIM];
    const __nv_bfloat16* wbaseL = &g_w1t[side][1][(size_t)nh * 128 * DDIM];

    float c[4][4][4];
    #pragma unroll
    for (int mt = 0; mt < 4; mt++)
        #pragma unroll
        for (int nt = 0; nt < 4; nt++)
            #pragma unroll
            for (int q = 0; q < 4; q++) c[mt][nt][q] = 0.f;

    const uint32_t uaHi = smem_u32(aHi), uaLo = smem_u32(aLo);
    const uint32_t uwHi = smem_u32(wHi), uwLo = smem_u32(wLo);

    const uint32_t aOff = (uint32_t)(wm * 64 + (lane & 15)) * 144 + (lane >> 4) * 16;
    const uint32_t bOff = (uint32_t)(wn * 32 + (lane & 7) + ((lane >> 4) << 3)) * 144
                        + ((lane >> 3) & 1) * 16;

    for (int ck = 0; ck < 4; ck++) {
        if (ck) __syncthreads();

        #pragma unroll
        for (int p = 0; p < 8; p++) {
            int idx = p * 256 + tid;
            int r   = idx >> 4;
            int d4  = (idx & 15) * 4;
            uint32_t so = (uint32_t)r * 144 + d4 * 2;

            float4 f = *(const float4*)(asrc[p] + ck * 64);
            uint32_t h0 = bfpack(f.x, f.y);
            uint32_t h1 = bfpack(f.z, f.w);
            float hx = __uint_as_float(h0 << 16);
            float hy = __uint_as_float(h0 & 0xFFFF0000u);
            float hz = __uint_as_float(h1 << 16);
            float hw = __uint_as_float(h1 & 0xFFFF0000u);
            uint32_t l0 = bfpack(f.x - hx, f.y - hy);
            uint32_t l1 = bfpack(f.z - hz, f.w - hw);
            *(uint2*)(aHi + so) = make_uint2(h0, h1);
            *(uint2*)(aLo + so) = make_uint2(l0, l1);

            size_t woff = (size_t)r * DDIM + ck * 64 + d4;
            *(uint2*)(wHi + so) = *(const uint2*)(wbaseH + woff);
            *(uint2*)(wLo + so) = *(const uint2*)(wbaseL + woff);
        }
        __syncthreads();

        #pragma unroll
        for (int ks = 0; ks < 4; ks++) {
            uint32_t ah[4][4], al[4][4], bh[2][4], bl[2][4];
            #pragma unroll
            for (int mt = 0; mt < 4; mt++) {
                uint32_t ao = aOff + (uint32_t)mt * (16 * 144) + ks * 32;
                LDSM4(ah[mt], uaHi + ao);
                LDSM4(al[mt], uaLo + ao);
            }
            #pragma unroll
            for (int nt2 = 0; nt2 < 2; nt2++) {
                uint32_t bo = bOff + (uint32_t)nt2 * (16 * 144) + ks * 32;
                LDSM4(bh[nt2], uwHi + bo);
                LDSM4(bl[nt2], uwLo + bo);
            }
            #pragma unroll
            for (int mt = 0; mt < 4; mt++) {
                #pragma unroll
                for (int nt = 0; nt < 4; nt++) {
                    int n2 = nt >> 1, s2 = (nt & 1) * 2;
                    MMA_BF16(c[mt][nt], ah[mt], bh[n2][s2], bh[n2][s2 + 1]);
                    MMA_BF16(c[mt][nt], ah[mt], bl[n2][s2], bl[n2][s2 + 1]);
                    MMA_BF16(c[mt][nt], al[mt], bh[n2][s2], bh[n2][s2 + 1]);
                }
            }
        }
    }

    const float bsel = side ? 1.0f : 0.0f;
    #pragma unroll
    for (int mt = 0; mt < 4; mt++) {
        #pragma unroll
        for (int nt = 0; nt < 4; nt++) {
            int a0 = wm * 64 + mt * 16 + (lane >> 2);
            int cl = wn * 32 + nt * 8 + (lane & 3) * 2;
            float bx = bsel * b1s[cl], by = bsel * b1s[cl + 1];
            float* base = &g_hT[side][((size_t)(n * HDIM + nh * 128 + cl)) * LDIM + a0];
            base[0]            = c[mt][nt][0] + bx;
            base[LDIM]         = c[mt][nt][1] + by;
            base[8]            = c[mt][nt][2] + bx;
            base[LDIM + 8]     = c[mt][nt][3] + by;
        }
    }
}

// ---------------------------------------------------------------------------
// Kernel B: pairwise relu-score + fused 4x4 patch sum, H-split x8.
// Block = (hs, qa, qb, n): 32-h slice, 64x64 pair tile; 128 threads.
// Thread = 8a x 4b (TWO patches stacked in I): 3 LDS.128 per hh feed 96 lanes.
// ---------------------------------------------------------------------------
__global__ void __launch_bounds__(128) pair_kernel(const float* __restrict__ W2)
{
    const int n  = blockIdx.y;
    const int hs = blockIdx.x >> 2;
    const int qa = (blockIdx.x >> 1) & 1;
    const int qb = blockIdx.x & 1;
    const int tx = threadIdx.x & 15;   // J patch
    const int ty = threadIdx.x >> 4;   // I patch-pair (0..7)

    __shared__ float h0s[32][64];
    __shared__ float h1s[32][64];
    __shared__ float w2s[32];

    if (threadIdx.x < 32) w2s[threadIdx.x] = W2[hs * 32 + threadIdx.x];

    const float* h0g = &g_hT[0][((size_t)n * HDIM + hs * 32) * LDIM + qa * 64];
    const float* h1g = &g_hT[1][((size_t)n * HDIM + hs * 32) * LDIM + qb * 64];

    #pragma unroll
    for (int i = 0; i < 4; i++) {
        int idx = i * 128 + threadIdx.x;     // 0..511 float4 slots
        int hl = idx >> 4, al = (idx & 15) * 4;
        *(float4*)&h0s[hl][al] = *(const float4*)&h0g[(size_t)hl * LDIM + al];
        *(float4*)&h1s[hl][al] = *(const float4*)&h1g[(size_t)hl * LDIM + al];
    }
    __syncthreads();

    float acc0 = 0.f, acc1 = 0.f;

    #pragma unroll 8
    for (int hh = 0; hh < 32; hh++) {
        float4 aA = *(const float4*)&h0s[hh][ty * 8];
        float4 aB = *(const float4*)&h0s[hh][ty * 8 + 4];
        float4 b4 = *(const float4*)&h1s[hh][tx * 4];

        float s0 =
            (((fmaxf(aA.x + b4.x, 0.f) + fmaxf(aA.x + b4.y, 0.f)) +
              (fmaxf(aA.x + b4.z, 0.f) + fmaxf(aA.x + b4.w, 0.f))) +
             ((fmaxf(aA.y + b4.x, 0.f) + fmaxf(aA.y + b4.y, 0.f)) +
              (fmaxf(aA.y + b4.z, 0.f) + fmaxf(aA.y + b4.w, 0.f)))) +
            (((fmaxf(aA.z + b4.x, 0.f) + fmaxf(aA.z + b4.y, 0.f)) +
              (fmaxf(aA.z + b4.z, 0.f) + fmaxf(aA.z + b4.w, 0.f))) +
             ((fmaxf(aA.w + b4.x, 0.f) + fmaxf(aA.w + b4.y, 0.f)) +
              (fmaxf(aA.w + b4.z, 0.f) + fmaxf(aA.w + b4.w, 0.f))));

        float s1 =
            (((fmaxf(aB.x + b4.x, 0.f) + fmaxf(aB.x + b4.y, 0.f)) +
              (fmaxf(aB.x + b4.z, 0.f) + fmaxf(aB.x + b4.w, 0.f))) +
             ((fmaxf(aB.y + b4.x, 0.f) + fmaxf(aB.y + b4.y, 0.f)) +
              (fmaxf(aB.y + b4.z, 0.f) + fmaxf(aB.y + b4.w, 0.f)))) +
            (((fmaxf(aB.z + b4.x, 0.f) + fmaxf(aB.z + b4.y, 0.f)) +
              (fmaxf(aB.z + b4.z, 0.f) + fmaxf(aB.z + b4.w, 0.f))) +
             ((fmaxf(aB.w + b4.x, 0.f) + fmaxf(aB.w + b4.y, 0.f)) +
              (fmaxf(aB.w + b4.z, 0.f) + fmaxf(aB.w + b4.w, 0.f))));

        float w = w2s[hh];
        acc0 = fmaf(w, s0, acc0);
        acc1 = fmaf(w, s1, acc1);
    }

    const int I0 = qa * 16 + ty * 2;
    const int J  = qb * 16 + tx;
    g_part[hs][n * 1024 + I0 * 32 + J]       = acc0;
    g_part[hs][n * 1024 + (I0 + 1) * 32 + J] = acc1;
}

// ---------------------------------------------------------------------------
// Kernel R: deterministic reduce of the 8 H-partials + bias, plus the
// constant pairs tensor (merged).
// ---------------------------------------------------------------------------
__global__ void __launch_bounds__(256) reduce_kernel(
    const float* __restrict__ b2, float* __restrict__ out, int write_pairs)
{
    int i = blockIdx.x * 256 + threadIdx.x;   // 0..32767
    float s = ((g_part[0][i] + g_part[1][i]) + (g_part[2][i] + g_part[3][i]))
            + ((g_part[4][i] + g_part[5][i]) + (g_part[6][i] + g_part[7][i]));
    out[i] = s + 16.0f * b2[0];
    if (write_pairs) {
        int p = i & 1023;
        out[32768 + 2 * i]     = (float)(p >> 5);
        out[32768 + 2 * i + 1] = (float)(p & 31);
    }
}

extern "C" void kernel_launch(void* const* d_in, const int* in_sizes, int n_in,
                              void* d_out, int out_size)
{
    const float* fea  = (const float*)d_in[0];
    const int*   ind0 = (const int*)  d_in[1];
    const int*   ind1 = (const int*)  d_in[2];

    int base = 3;
    if (n_in >= 9 && in_sizes[3] == 1) base = 4;

    const float* W1a = (const float*)d_in[base + 0];
    const float* W1b = (const float*)d_in[base + 1];
    const float* b1  = (const float*)d_in[base + 2];
    const float* W2  = (const float*)d_in[base + 3];
    const float* b2  = (const float*)d_in[base + 4];

    float* out = (float*)d_out;

    const int dyn_bytes = 4 * 128 * 144;   // 73728
    cudaFuncSetAttribute(gemm_kernel, cudaFuncAttributeMaxDynamicSharedMemorySize,
                         dyn_bytes);

    w1t_kernel<<<dim3(8, 8, 2), dim3(32, 8)>>>(W1a, W1b);
    gemm_kernel<<<dim3(2, 2, NUMB), 256, dyn_bytes>>>(fea, ind0, ind1, b1);
    pair_kernel<<<dim3(32, NUMB), 128>>>(W2);
    reduce_kernel<<<128, 256>>>(b2, out, out_size >= 98304 ? 1 : 0);
}